// round 8
// baseline (speedup 1.0000x reference)
#include <cuda_runtime.h>
#include <cuda_fp16.h>
#include <cstdint>

#define TOTAL_ELEMS 33554432

__device__ __align__(128) float g_acc[TOTAL_ELEMS];
__device__ __align__(128) __half g_xhi[TOTAL_ELEMS];
__device__ __align__(128) __half g_whi[3342336];

// ---- smem: 4 stages of { A 128x144B | B 64x144B } ----
#define APITCH 144
#define ASZ (128 * APITCH)          // 18432
#define BOFF ASZ
#define BSZ (64 * APITCH)           // 9216
#define STG (ASZ + BSZ)             // 27648
#define DYN_SMEM (4 * STG)          // 110592; 2 CTA/SM = 221184

__device__ __forceinline__ uint32_t smem_u32(const void* p) {
    uint32_t a;
    asm("{ .reg .u64 t; cvta.to.shared.u64 t, %1; cvt.u32.u64 %0, t; }" : "=r"(a) : "l"(p));
    return a;
}
__device__ __forceinline__ void ldsm4(uint32_t* r, uint32_t a) {
    asm volatile("ldmatrix.sync.aligned.m8n8.x4.shared.b16 {%0,%1,%2,%3}, [%4];"
        : "=r"(r[0]), "=r"(r[1]), "=r"(r[2]), "=r"(r[3]) : "r"(a));
}
__device__ __forceinline__ void mma16816(float* d, const uint32_t* a, const uint32_t* b) {
    asm volatile("mma.sync.aligned.m16n8k16.row.col.f32.f16.f16.f32 "
        "{%0,%1,%2,%3}, {%4,%5,%6,%7}, {%8,%9}, {%0,%1,%2,%3};"
        : "+f"(d[0]), "+f"(d[1]), "+f"(d[2]), "+f"(d[3])
        : "r"(a[0]), "r"(a[1]), "r"(a[2]), "r"(a[3]), "r"(b[0]), "r"(b[1]));
}
__device__ __forceinline__ void cpa16(uint32_t s, const void* g) {
    asm volatile("cp.async.cg.shared.global [%0], [%1], 16;" :: "r"(s), "l"(g));
}
#define CPA_COMMIT() asm volatile("cp.async.commit_group;" ::: "memory")
#define CPA_WAITG(k) asm volatile("cp.async.wait_group %0;" :: "n"(k) : "memory")

// ================= prep: X fp32 (original) -> fp16 (permuted, c fastest) ==========
__global__ __launch_bounds__(256) void prep_x(const float* __restrict__ X)
{
    __shared__ float ts[64][65];
    const int b = blockIdx.x >> 12, sblk = blockIdx.x & 4095;
    const size_t s0 = (size_t)sblk * 64;
    const int t = threadIdx.x, sl = t & 63, ch = t >> 6;
    const float* xp = X + (size_t)b * 64 * 262144 + s0;
    #pragma unroll
    for (int i = 0; i < 16; i++) {
        const int c = ch + i * 4;
        ts[sl][c] = xp[(size_t)c * 262144 + sl];
    }
    __syncthreads();
    const int srow = t >> 2, sub = t & 3;
    const size_t row = (size_t)b * 262144 + s0 + srow;
    __half* hp = g_xhi + row * 64 + sub * 16;
    #pragma unroll
    for (int j = 0; j < 16; j++)
        hp[j] = __float2half(ts[srow][sub * 16 + j]);
}

__global__ __launch_bounds__(256) void prep_w(const float* __restrict__ W, int woff, int n)
{
    const int row = blockIdx.x;
    const float* wp = W + (size_t)row * n;
    __half* hp = g_whi + woff + (size_t)row * n;
    for (int c = threadIdx.x; c < n; c += 256)
        hp[c] = __float2half(wp[c]);
}

// ===================== shared fused-GEMM mainloop =====================
// acc: 128 rows x 64 cols. 8 warps: wm (rows wm*32..+32) x wn (cols wn*32..+32).
// Chunk = 64 c_in of one s_in of one op. op = ck >> lognc.
__device__ __forceinline__ void gemm_fused(
    const uint32_t sb, const int tid,
    const int aRowBase,                       // g_xhi row for this thread's A row (m = tid>>1), excl. op parts
    const int* __restrict__ c0_s,             // smem [3]
    const int* __restrict__ step_s,           // smem [3]
    const long* __restrict__ wbyte_s,         // smem [3]: byte offset of W slice in g_whi
    const int nbytes,                         // W row pitch in bytes
    const int nchunk, const int lognc,
    float acc[2][4][4])
{
    const int lane = tid & 31, wid = tid >> 5;
    const int wm = wid & 3, wn = wid >> 2;
    const uint32_t aSm = (uint32_t)((tid >> 1) * APITCH + (tid & 1) * 64);
    const uint32_t bSm = (uint32_t)(BOFF + (tid >> 2) * APITCH + (tid & 3) * 32);
    const long bRowByte = (long)(tid >> 2) * nbytes + (tid & 3) * 32;
    const int ncm = (1 << lognc) - 1;

    auto issue = [&](int ck) {
        const int op = ck >> lognc, s = ck & ncm;
        const uint32_t st = sb + (uint32_t)((ck & 3) * STG);
        const char* ga = (const char*)g_xhi
            + ((size_t)(aRowBase + c0_s[op] + s * step_s[op])) * 128 + (tid & 1) * 64;
        cpa16(st + aSm,      ga);
        cpa16(st + aSm + 16, ga + 16);
        cpa16(st + aSm + 32, ga + 32);
        cpa16(st + aSm + 48, ga + 48);
        const char* gb = (const char*)g_whi + wbyte_s[op] + bRowByte + (size_t)s * 128;
        cpa16(st + bSm,      gb);
        cpa16(st + bSm + 16, gb + 16);
    };

    const uint32_t a_lm = (uint32_t)(wm * 32 * APITCH + (lane & 15) * APITCH + (lane >> 4) * 16);
    const uint32_t b_lm = (uint32_t)(BOFF + wn * 32 * APITCH
        + (((lane >> 4) & 1) * 8 + (lane & 7)) * APITCH + ((lane >> 3) & 1) * 16);

    issue(0); CPA_COMMIT();
    issue(1); CPA_COMMIT();
    issue(2); CPA_COMMIT();

    for (int ck = 0; ck < nchunk; ck++) {
        if (ck + 1 < nchunk) CPA_WAITG(2); else CPA_WAITG(0);
        __syncthreads();
        if (ck + 3 < nchunk) { issue(ck + 3); CPA_COMMIT(); }

        const uint32_t st = sb + (uint32_t)((ck & 3) * STG);
        #pragma unroll
        for (int k = 0; k < 4; k++) {
            uint32_t av[2][4], bv[4];
            ldsm4(av[0], st + a_lm + k * 32);
            ldsm4(av[1], st + a_lm + 16 * APITCH + k * 32);
            #pragma unroll
            for (int ntp = 0; ntp < 2; ntp++) {
                ldsm4(bv, st + b_lm + ntp * 16 * APITCH + k * 32);
                mma16816(acc[0][2 * ntp],     av[0], bv);
                mma16816(acc[0][2 * ntp + 1], av[0], bv + 2);
                mma16816(acc[1][2 * ntp],     av[1], bv);
                mma16816(acc[1][2 * ntp + 1], av[1], bv + 2);
            }
        }
    }
}

// stage acc -> Cs[128][65] fp32 (reuses pipeline smem)
__device__ __forceinline__ void stage_acc(float* Cs, const int tid, float acc[2][4][4])
{
    const int lane = tid & 31, wid = tid >> 5;
    const int wm = wid & 3, wn = wid >> 2;
    const int r0 = lane >> 2, cp = (lane & 3) * 2;
    __syncthreads();
    #pragma unroll
    for (int mt = 0; mt < 2; mt++) {
        const int rb = wm * 32 + mt * 16 + r0;
        #pragma unroll
        for (int nt = 0; nt < 4; nt++) {
            const int cc = wn * 32 + nt * 8 + cp;
            Cs[rb * 65 + cc]           = acc[mt][nt][0];
            Cs[rb * 65 + cc + 1]       = acc[mt][nt][1];
            Cs[(rb + 8) * 65 + cc]     = acc[mt][nt][2];
            Cs[(rb + 8) * 65 + cc + 1] = acc[mt][nt][3];
        }
    }
    __syncthreads();
}

// ============== patch_fused: ops p,q,r -> write g_acc (no RMW) ==============
// grid: (64 pqr, 64 j). rows: m = b*64 + g, dhw = j*64+g.
__global__ __launch_bounds__(256, 2)
void patch_fused(const float* __restrict__ b_pd, const float* __restrict__ b_ph,
                 const float* __restrict__ b_pw)
{
    extern __shared__ __align__(16) char dsm[];
    __shared__ int c0_s[3], step_s[3];
    __shared__ long wbyte_s[3];

    const int tid = threadIdx.x;
    const int pqr = blockIdx.x, j = blockIdx.y;
    const int p = pqr >> 4, q = (pqr >> 2) & 3, r = pqr & 3;

    if (tid == 0) {
        c0_s[0] = q * 4 + r;      step_s[0] = 16;
        c0_s[1] = p * 16 + r;     step_s[1] = 4;
        c0_s[2] = p * 16 + q * 4; step_s[2] = 1;
        wbyte_s[0] = (long)(3145728 + p * 64 * 256) * 2;
        wbyte_s[1] = (long)(3211264 + q * 64 * 256) * 2;
        wbyte_s[2] = (long)(3276800 + r * 64 * 256) * 2;
    }
    __syncthreads();

    const int mA = tid >> 1;
    const int aRowBase = (mA >> 6) * 262144 + (j * 64 + (mA & 63)) * 64;

    float acc[2][4][4];
    #pragma unroll
    for (int i = 0; i < 2; i++)
        #pragma unroll
        for (int jj = 0; jj < 4; jj++)
            #pragma unroll
            for (int u = 0; u < 4; u++) acc[i][jj][u] = 0.f;

    gemm_fused(smem_u32(dsm), tid, aRowBase, c0_s, step_s, wbyte_s, 512, 12, 2, acc);

    float* Cs = (float*)dsm;
    stage_acc(Cs, tid, acc);

    // bias per c (fixed across rows)
    const int li = tid & 15, c4 = li * 4;
    float bs[4];
    #pragma unroll
    for (int u = 0; u < 4; u++)
        bs[u] = __ldg(b_pd + p * 64 + c4 + u) + __ldg(b_ph + q * 64 + c4 + u)
              + __ldg(b_pw + r * 64 + c4 + u);

    const int rgrp = tid >> 4;
    #pragma unroll
    for (int it = 0; it < 8; it++) {
        const int m = it * 16 + rgrp;
        const int b = m >> 6, g = m & 63;
        const size_t R = (size_t)b * 262144 + (size_t)(j * 64 + g) * 64 + pqr;
        float4 v;
        v.x = Cs[m * 65 + c4]     + bs[0];
        v.y = Cs[m * 65 + c4 + 1] + bs[1];
        v.z = Cs[m * 65 + c4 + 2] + bs[2];
        v.w = Cs[m * 65 + c4 + 3] + bs[3];
        *(float4*)(g_acc + R * 64 + c4) = v;
    }
}

// ========= image_fused: ops d,h,w + g_acc + bias -> leaky -> +X -> Y =========
// grid: 4096 (dhw). rows: m = b*64 + pqr.
__global__ __launch_bounds__(256, 2)
void image_fused(const float* __restrict__ X, float* __restrict__ Y,
                 const float* __restrict__ b_d, const float* __restrict__ b_h,
                 const float* __restrict__ b_w)
{
    extern __shared__ __align__(16) char dsm[];
    __shared__ int c0_s[3], step_s[3];
    __shared__ long wbyte_s[3];

    const int tid = threadIdx.x;
    const int dhw = blockIdx.x;
    const int d = dhw >> 8, h = (dhw >> 4) & 15, w_ = dhw & 15;

    if (tid == 0) {
        c0_s[0] = h * 1024 + w_ * 64;  step_s[0] = 16384;
        c0_s[1] = d * 16384 + w_ * 64; step_s[1] = 1024;
        c0_s[2] = d * 16384 + h * 1024; step_s[2] = 64;
        wbyte_s[0] = (long)(0       + d * 64 * 1024) * 2;
        wbyte_s[1] = (long)(1048576 + h * 64 * 1024) * 2;
        wbyte_s[2] = (long)(2097152 + w_ * 64 * 1024) * 2;
    }
    __syncthreads();

    const int mA = tid >> 1;
    const int aRowBase = (mA >> 6) * 262144 + (mA & 63);

    float acc[2][4][4];
    #pragma unroll
    for (int i = 0; i < 2; i++)
        #pragma unroll
        for (int jj = 0; jj < 4; jj++)
            #pragma unroll
            for (int u = 0; u < 4; u++) acc[i][jj][u] = 0.f;

    gemm_fused(smem_u32(dsm), tid, aRowBase, c0_s, step_s, wbyte_s, 2048, 48, 4, acc);

    float* Cs = (float*)dsm;
    stage_acc(Cs, tid, acc);

    const int li = tid & 15, c4 = li * 4;
    float bi[4];
    #pragma unroll
    for (int u = 0; u < 4; u++)
        bi[u] = __ldg(b_d + d * 64 + c4 + u) + __ldg(b_h + h * 64 + c4 + u)
              + __ldg(b_w + w_ * 64 + c4 + u);

    // pass 1: Cs += g_acc row + bias (coalesced g_acc read)
    const int rgrp = tid >> 4;
    #pragma unroll
    for (int it = 0; it < 8; it++) {
        const int m = it * 16 + rgrp;
        const int b = m >> 6, pqr = m & 63;
        const size_t R = (size_t)b * 262144 + (size_t)dhw * 64 + pqr;
        const float4 gv = *(const float4*)(g_acc + R * 64 + c4);
        Cs[m * 65 + c4]     += gv.x + bi[0];
        Cs[m * 65 + c4 + 1] += gv.y + bi[1];
        Cs[m * 65 + c4 + 2] += gv.z + bi[2];
        Cs[m * 65 + c4 + 3] += gv.w + bi[3];
    }
    __syncthreads();

    // pass 2: leaky + residual, write Y in original layout (256B runs)
    #pragma unroll
    for (int it = 0; it < 8; it++) {
        const int pair = it * 16 + rgrp;
        const int c = pair >> 1, b = pair & 1;
        const int m0 = b * 64 + li * 4;
        float v[4];
        #pragma unroll
        for (int u = 0; u < 4; u++) {
            float a = Cs[(m0 + u) * 65 + c];
            v[u] = (a > 0.f ? a : 0.01f * a);
        }
        const size_t off = ((size_t)(b * 64 + c)) * 262144 + (size_t)dhw * 64 + li * 4;
        const float4 xv = *(const float4*)(X + off);
        float4 y;
        y.x = xv.x + v[0]; y.y = xv.y + v[1]; y.z = xv.z + v[2]; y.w = xv.w + v[3];
        *(float4*)(Y + off) = y;
    }
}

extern "C" void kernel_launch(void* const* d_in, const int* in_sizes, int n_in,
                              void* d_out, int out_size)
{
    const float* x    = (const float*)d_in[0];
    const float* w_d  = (const float*)d_in[1];
    const float* b_d  = (const float*)d_in[2];
    const float* w_h  = (const float*)d_in[3];
    const float* b_h  = (const float*)d_in[4];
    const float* w_w  = (const float*)d_in[5];
    const float* b_w  = (const float*)d_in[6];
    const float* w_pd = (const float*)d_in[7];
    const float* b_pd = (const float*)d_in[8];
    const float* w_ph = (const float*)d_in[9];
    const float* b_ph = (const float*)d_in[10];
    const float* w_pw = (const float*)d_in[11];
    const float* b_pw = (const float*)d_in[12];

    cudaFuncSetAttribute(patch_fused, cudaFuncAttributeMaxDynamicSharedMemorySize, DYN_SMEM);
    cudaFuncSetAttribute(image_fused, cudaFuncAttributeMaxDynamicSharedMemorySize, DYN_SMEM);

    prep_x<<<8192, 256>>>(x);
    prep_w<<<1024, 256>>>(w_d,  0,       1024);
    prep_w<<<1024, 256>>>(w_h,  1048576, 1024);
    prep_w<<<1024, 256>>>(w_w,  2097152, 1024);
    prep_w<<<256,  256>>>(w_pd, 3145728, 256);
    prep_w<<<256,  256>>>(w_ph, 3211264, 256);
    prep_w<<<256,  256>>>(w_pw, 3276800, 256);

    patch_fused<<<dim3(64, 64), 256, DYN_SMEM>>>(b_pd, b_ph, b_pw);
    image_fused<<<4096, 256, DYN_SMEM>>>(x, (float*)d_out, b_d, b_h, b_w);
}